// round 16
// baseline (speedup 1.0000x reference)
#include <cuda_runtime.h>
#include <cuda_fp16.h>
#include <math.h>

#define B_DIM  16
#define N_DIM  196608
#define TPB    256
#define NSLICE 24                 // blocks per batch
#define GRID   (B_DIM * NSLICE)   // 384 blocks; 3 CTA/SM * 148 = 444 >= 384
#define NACC   27                 // 21 sym H entries + 6 g entries
#define PPB    (N_DIM / NSLICE)   // 8192 points per block (contiguous chunk)
#define ITER1  (PPB / TPB)        // 32 phase-1 iterations
#define ITER3  (PPB / (4 * TPB))  // 8 phase-3 iterations (4 pts/thread)
#define SMEM_DYN (PPB * 8)        // 64 KB: planes 0+1 (ih0..ih3) per point

// Fixed-slot partials: [value 0..26][batch][slice]
__device__ float g_part[NACC * B_DIM * NSLICE];

// per-batch barrier state (generation monotonic across graph replays)
__device__ unsigned int g_bcnt[B_DIM];
__device__ volatile unsigned int g_bgen[B_DIM];

// global scratch (only 6 B/point): plane2 = (ih4,ih5) half2, gd = half
__device__ __align__(16) __half2 g_scr2[(size_t)B_DIM * N_DIM];
__device__ __align__(16) __half  g_scrg[(size_t)B_DIM * N_DIM];

// ---------------------------------------------------------------------------
// Per-batch barrier: only the NSLICE blocks of one batch synchronize.
// All blocks resident (GRID=384 <= 444 capacity) -> no deadlock.
// ---------------------------------------------------------------------------
__device__ __forceinline__ void batch_barrier(int b)
{
    __syncthreads();
    if (threadIdx.x == 0) {
        const unsigned int my = g_bgen[b];   // volatile read, before arrive
        __threadfence();
        const unsigned int prev = atomicAdd(&g_bcnt[b], 1u);
        if (prev == NSLICE - 1) {
            g_bcnt[b] = 0;
            __threadfence();
            g_bgen[b] = my + 1;              // release
        } else {
            while (g_bgen[b] == my) { __nanosleep(64); }
        }
        __threadfence();
    }
    __syncthreads();
}

__device__ __forceinline__ unsigned int pack_h2(float a, float b) {
    const __half2 h = __floats2half2_rn(a, b);
    return *(const unsigned int*)&h;
}

// ---------------------------------------------------------------------------
// Single fused kernel; per-block contiguous chunk so ih0..ih3 scratch lives
// in SMEM across the barrier (never touches L2/DRAM).
// ---------------------------------------------------------------------------
__global__ void __launch_bounds__(TPB, 3) dba_kernel(
    const float* __restrict__ r, const float* __restrict__ w,
    const float* __restrict__ Jp, const float* __restrict__ Jd,
    const float* __restrict__ lmbda, float* __restrict__ out)
{
    extern __shared__ __align__(16) uint2 s01[];   // [PPB]: (ih0,ih1),(ih2,ih3)

    const int b     = blockIdx.x / NSLICE;
    const int slice = blockIdx.x % NSLICE;
    const float lam = __ldg(lmbda + b);

    float* __restrict__ out_pose  = out;
    float* __restrict__ out_depth = out + B_DIM * 6;

    const size_t chunk = (size_t)b * N_DIM + (size_t)slice * PPB;

    // ===================== Phase 1: streaming reduction =====================
    float acc[NACC];
#pragma unroll
    for (int i = 0; i < NACC; i++) acc[i] = 0.f;

    for (int k = 0; k < ITER1; k++) {
        const int    l = k * TPB + threadIdx.x;    // local point index
        const size_t p = chunk + (size_t)l;

        const float2 rv = *(const float2*)(r  + 2 * p);
        const float2 wv = *(const float2*)(w  + 2 * p);
        const float2 jd = *(const float2*)(Jd + 2 * p);
        const float4 a0 = *(const float4*)(Jp + 12 * p);
        const float4 a1 = *(const float4*)(Jp + 12 * p + 4);
        const float4 a2 = *(const float4*)(Jp + 12 * p + 8);
        const float jp0[6] = {a0.x, a0.y, a0.z, a0.w, a1.x, a1.y};
        const float jp1[6] = {a1.z, a1.w, a2.x, a2.y, a2.z, a2.w};

        const float conf = wv.x;
        const float nl   = wv.y;

        float hpd[6];
#pragma unroll
        for (int i = 0; i < 6; i++)
            hpd[i] = conf * fmaf(jd.x, jp0[i], jd.y * jp1[i]);

        const float hdd = conf * fmaf(jd.x, jd.x, jd.y * jd.y);
        const float gd  = conf * fmaf(jd.x, rv.x, jd.y * rv.y);
        const float inv = 1.0f / fmaxf(hdd + lam + nl, 1e-4f);

        float cj0[6], cj1[6], ih[6];
#pragma unroll
        for (int i = 0; i < 6; i++) {
            cj0[i] = conf * jp0[i];
            cj1[i] = conf * jp1[i];
            ih[i]  = inv * hpd[i];
        }

        // scratch: planes 0+1 -> SMEM (8 B, lane-contiguous, conflict-free)
        s01[l] = make_uint2(pack_h2(ih[0], ih[1]), pack_h2(ih[2], ih[3]));
        // plane2 + gd -> global (6 B/pt)
        g_scr2[p] = __floats2half2_rn(ih[4], ih[5]);
        g_scrg[p] = __float2half_rn(inv * gd);

        int idx = 0;
#pragma unroll
        for (int i = 0; i < 6; i++) {
#pragma unroll
            for (int j = i; j < 6; j++) {
                float t = acc[idx];
                t = fmaf(cj0[i], jp0[j], t);
                t = fmaf(cj1[i], jp1[j], t);
                t = fmaf(-ih[i], hpd[j], t);
                acc[idx++] = t;
            }
        }
#pragma unroll
        for (int i = 0; i < 6; i++) {
            float t = acc[21 + i];
            t = fmaf(cj0[i], rv.x, t);
            t = fmaf(cj1[i], rv.y, t);
            t = fmaf(-ih[i], gd, t);
            acc[21 + i] = t;
        }
    }

    // block-level reduce
#pragma unroll
    for (int off = 16; off; off >>= 1) {
#pragma unroll
        for (int i = 0; i < NACC; i++)
            acc[i] += __shfl_down_sync(0xFFFFFFFFu, acc[i], off);
    }

    __shared__ float sh[TPB / 32][NACC];
    const int wid  = threadIdx.x >> 5;
    const int lane = threadIdx.x & 31;
    if (lane == 0) {
#pragma unroll
        for (int i = 0; i < NACC; i++) sh[wid][i] = acc[i];
    }
    __syncthreads();

    if (threadIdx.x < NACC) {
        float s = 0.f;
#pragma unroll
        for (int wgi = 0; wgi < TPB / 32; wgi++) s += sh[wgi][threadIdx.x];
        g_part[threadIdx.x * (B_DIM * NSLICE) + b * NSLICE + slice] = s;
    }

    batch_barrier(b);

    // ========== Phase 2: redundant per-block final reduce + LU solve ========
    __shared__ float sums[NACC];
    __shared__ float dpsh[6];
    if (threadIdx.x < NACC) {
        const float* pp = g_part + threadIdx.x * (B_DIM * NSLICE) + b * NSLICE;
        float t = 0.f;
#pragma unroll
        for (int i = 0; i < NSLICE; i++) t += pp[i];
        sums[threadIdx.x] = t;
    }
    __syncthreads();

    if (threadIdx.x == 0) {
        float M[6][6], gv[6], x[6];
        int idx = 0;
        for (int i = 0; i < 6; i++)
            for (int j = i; j < 6; j++) {
                const float v = sums[idx++];
                M[i][j] = v; M[j][i] = v;
            }
        const float dd = lam + 0.011f;
        for (int i = 0; i < 6; i++) M[i][i] += dd;
        for (int i = 0; i < 6; i++) gv[i] = sums[21 + i];

        for (int c = 0; c < 6; c++) {
            int piv = c; float mx = fabsf(M[c][c]);
            for (int rr = c + 1; rr < 6; rr++) {
                const float a = fabsf(M[rr][c]);
                if (a > mx) { mx = a; piv = rr; }
            }
            if (piv != c) {
                for (int j = 0; j < 6; j++) {
                    const float tmp = M[c][j]; M[c][j] = M[piv][j]; M[piv][j] = tmp;
                }
                const float tmp = gv[c]; gv[c] = gv[piv]; gv[piv] = tmp;
            }
            float d = M[c][c];
            if (d == 0.f) d = 1e-30f;
            const float invd = 1.0f / d;
            for (int rr = c + 1; rr < 6; rr++) {
                const float f = M[rr][c] * invd;
                for (int j = c; j < 6; j++) M[rr][j] -= f * M[c][j];
                gv[rr] -= f * gv[c];
            }
        }
        for (int i = 5; i >= 0; i--) {
            float s = gv[i];
            for (int j = i + 1; j < 6; j++) s -= M[i][j] * x[j];
            x[i] = s / M[i][i];
        }

#pragma unroll
        for (int i = 0; i < 6; i++) dpsh[i] = x[i];   // unclipped, for depth
        if (slice == 0) {
            for (int i = 0; i < 6; i++)
                out_pose[b * 6 + i] = fminf(fmaxf(x[i], -2.0f), 2.0f);
        }
    }
    __syncthreads();

    float2 dpp[3];
#pragma unroll
    for (int k = 0; k < 3; k++) {
        dpp[k].x = dpsh[2 * k];
        dpp[k].y = dpsh[2 * k + 1];
    }

    // ========= Phase 3: depth for own contiguous chunk (smem + 6B gmem) =====
    for (int it = 0; it < ITER3; it++) {
        const int    q = it * TPB + threadIdx.x;      // quad index in chunk
        const int    l = q * 4;                        // first local point
        const size_t p = chunk + (size_t)l;

        // smem planes 0+1 for 4 points: 32 B contiguous
        const uint4 sA = ((const uint4*)s01)[q * 2];
        const uint4 sB = ((const uint4*)s01)[q * 2 + 1];
        // global plane2 (4x half2 = 16 B) + gd (4x half = 8 B)
        const uint4 u2 = *(const uint4*)(g_scr2 + p);
        const uint2 fg = *(const uint2*)(g_scrg + p);

        const float2 g01 = __half22float2(*(const __half2*)&fg.x);
        const float2 g23 = __half22float2(*(const __half2*)&fg.y);
        float res[4] = {g01.x, g01.y, g23.x, g23.y};

        // point j: planes01 from sA/sB, plane2 from u2
        const unsigned int p01[4][2] = {{sA.x, sA.y}, {sA.z, sA.w},
                                        {sB.x, sB.y}, {sB.z, sB.w}};
        const unsigned int p2[4] = {u2.x, u2.y, u2.z, u2.w};
#pragma unroll
        for (int j = 0; j < 4; j++) {
            const float2 q0 = __half22float2(*(const __half2*)&p01[j][0]);
            const float2 q1 = __half22float2(*(const __half2*)&p01[j][1]);
            const float2 q2 = __half22float2(*(const __half2*)&p2[j]);
            res[j] = fmaf(-q0.x, dpp[0].x, fmaf(-q0.y, dpp[0].y, res[j]));
            res[j] = fmaf(-q1.x, dpp[1].x, fmaf(-q1.y, dpp[1].y, res[j]));
            res[j] = fmaf(-q2.x, dpp[2].x, fmaf(-q2.y, dpp[2].y, res[j]));
        }

        *(float4*)(out_depth + p) = make_float4(res[0], res[1], res[2], res[3]);
    }
}

// ---------------------------------------------------------------------------
extern "C" void kernel_launch(void* const* d_in, const int* in_sizes, int n_in,
                              void* d_out, int out_size)
{
    const float* r   = (const float*)d_in[0];
    const float* w   = (const float*)d_in[1];
    const float* Jp  = (const float*)d_in[2];
    const float* Jd  = (const float*)d_in[3];
    const float* lam = (const float*)d_in[4];
    float* out = (float*)d_out;

    cudaFuncSetAttribute(dba_kernel,
                         cudaFuncAttributeMaxDynamicSharedMemorySize, SMEM_DYN);
    dba_kernel<<<GRID, TPB, SMEM_DYN>>>(r, w, Jp, Jd, lam, out);
}

// round 17
// speedup vs baseline: 1.1722x; 1.1722x over previous
#include <cuda_runtime.h>
#include <cuda_fp16.h>
#include <math.h>

#define B_DIM  16
#define N_DIM  196608
#define TPB    256
#define NSLICE 27                 // blocks per batch (R13 grid: best occupancy)
#define GRID   (B_DIM * NSLICE)   // 432 blocks; 3 CTA/SM * 148 = 444 >= 432
#define NACC   27                 // 21 sym H entries + 6 g entries
#define QPB    (N_DIM / 4)        // depth quads per batch = 49152

// Fixed-slot partials: [value 0..26][batch][slice]
__device__ float g_part[NACC * B_DIM * NSLICE];

// per-batch barrier state (generation monotonic across graph replays)
__device__ unsigned int g_bcnt[B_DIM];
__device__ volatile unsigned int g_bgen[B_DIM];

#define SP ((size_t)B_DIM * N_DIM)
// half2 scratch: plane k holds (ih[2k], ih[2k+1]) per point
__device__ __align__(16) __half2 g_scrh[3 * B_DIM * N_DIM];
// half scratch: inv*gd per point (error proportional to value -> rel ~5e-4)
__device__ __align__(16) __half  g_scrf[B_DIM * N_DIM];

// ---------------------------------------------------------------------------
// Per-batch barrier: only the NSLICE blocks of one batch synchronize.
// Generation read BEFORE arrive; last arriver resets count and bumps gen.
// All blocks resident (GRID=432 <= 444 capacity) -> no deadlock.
// ---------------------------------------------------------------------------
__device__ __forceinline__ void batch_barrier(int b)
{
    __syncthreads();
    if (threadIdx.x == 0) {
        const unsigned int my = g_bgen[b];   // volatile read, before arrive
        __threadfence();
        const unsigned int prev = atomicAdd(&g_bcnt[b], 1u);
        if (prev == NSLICE - 1) {
            g_bcnt[b] = 0;
            __threadfence();
            g_bgen[b] = my + 1;              // release
        } else {
            while (g_bgen[b] == my) { __nanosleep(64); }
        }
        __threadfence();
    }
    __syncthreads();
}

// ---------------------------------------------------------------------------
// Single fused kernel: reduce -> per-batch barrier -> redundant solve -> depth
// Single-point inner loop (80 regs) to fit 3 CTAs/SM without spills.
// ---------------------------------------------------------------------------
__global__ void __launch_bounds__(TPB, 3) dba_kernel(
    const float* __restrict__ r, const float* __restrict__ w,
    const float* __restrict__ Jp, const float* __restrict__ Jd,
    const float* __restrict__ lmbda, float* __restrict__ out)
{
    const int b     = blockIdx.x / NSLICE;
    const int slice = blockIdx.x % NSLICE;
    const float lam = __ldg(lmbda + b);

    float* __restrict__ out_pose  = out;
    float* __restrict__ out_depth = out + B_DIM * 6;

    // ===================== Phase 1: streaming reduction =====================
    float acc[NACC];
#pragma unroll
    for (int i = 0; i < NACC; i++) acc[i] = 0.f;

    const size_t base = (size_t)b * N_DIM;

    for (int n = slice * TPB + threadIdx.x; n < N_DIM; n += NSLICE * TPB) {
        const size_t p = base + (size_t)n;
        const float2 rv = *(const float2*)(r  + 2 * p);
        const float2 wv = *(const float2*)(w  + 2 * p);
        const float2 jd = *(const float2*)(Jd + 2 * p);
        const float4 a0 = *(const float4*)(Jp + 12 * p);
        const float4 a1 = *(const float4*)(Jp + 12 * p + 4);
        const float4 a2 = *(const float4*)(Jp + 12 * p + 8);
        const float jp0[6] = {a0.x, a0.y, a0.z, a0.w, a1.x, a1.y};
        const float jp1[6] = {a1.z, a1.w, a2.x, a2.y, a2.z, a2.w};

        const float conf = wv.x;
        const float nl   = wv.y;

        float hpd[6];
#pragma unroll
        for (int i = 0; i < 6; i++)
            hpd[i] = conf * fmaf(jd.x, jp0[i], jd.y * jp1[i]);

        const float hdd = conf * fmaf(jd.x, jd.x, jd.y * jd.y);
        const float gd  = conf * fmaf(jd.x, rv.x, jd.y * rv.y);
        const float inv = 1.0f / fmaxf(hdd + lam + nl, 1e-4f);

        float cj0[6], cj1[6], ih[6];
#pragma unroll
        for (int i = 0; i < 6; i++) {
            cj0[i] = conf * jp0[i];
            cj1[i] = conf * jp1[i];
            ih[i]  = inv * hpd[i];
        }

        // scratch for depth pass (warp-dense, 14 B/point)
        g_scrh[0 * SP + p] = __floats2half2_rn(ih[0], ih[1]);
        g_scrh[1 * SP + p] = __floats2half2_rn(ih[2], ih[3]);
        g_scrh[2 * SP + p] = __floats2half2_rn(ih[4], ih[5]);
        g_scrf[p] = __float2half_rn(inv * gd);

        int idx = 0;
#pragma unroll
        for (int i = 0; i < 6; i++) {
#pragma unroll
            for (int j = i; j < 6; j++) {
                float t = acc[idx];
                t = fmaf(cj0[i], jp0[j], t);
                t = fmaf(cj1[i], jp1[j], t);
                t = fmaf(-ih[i], hpd[j], t);
                acc[idx++] = t;
            }
        }
#pragma unroll
        for (int i = 0; i < 6; i++) {
            float t = acc[21 + i];
            t = fmaf(cj0[i], rv.x, t);
            t = fmaf(cj1[i], rv.y, t);
            t = fmaf(-ih[i], gd, t);
            acc[21 + i] = t;
        }
    }

    // block-level reduce
#pragma unroll
    for (int off = 16; off; off >>= 1) {
#pragma unroll
        for (int i = 0; i < NACC; i++)
            acc[i] += __shfl_down_sync(0xFFFFFFFFu, acc[i], off);
    }

    __shared__ float sh[TPB / 32][NACC];
    const int wid  = threadIdx.x >> 5;
    const int lane = threadIdx.x & 31;
    if (lane == 0) {
#pragma unroll
        for (int i = 0; i < NACC; i++) sh[wid][i] = acc[i];
    }
    __syncthreads();

    if (threadIdx.x < NACC) {
        float s = 0.f;
#pragma unroll
        for (int wgi = 0; wgi < TPB / 32; wgi++) s += sh[wgi][threadIdx.x];
        g_part[threadIdx.x * (B_DIM * NSLICE) + b * NSLICE + slice] = s;
    }

    batch_barrier(b);

    // ========== Phase 2: redundant per-block final reduce + LU solve ========
    __shared__ float sums[NACC];
    __shared__ float dpsh[6];
    if (threadIdx.x < NACC) {
        const float* pp = g_part + threadIdx.x * (B_DIM * NSLICE) + b * NSLICE;
        float t = 0.f;
#pragma unroll
        for (int i = 0; i < NSLICE; i++) t += pp[i];
        sums[threadIdx.x] = t;
    }
    __syncthreads();

    if (threadIdx.x == 0) {
        float M[6][6], gv[6], x[6];
        int idx = 0;
        for (int i = 0; i < 6; i++)
            for (int j = i; j < 6; j++) {
                const float v = sums[idx++];
                M[i][j] = v; M[j][i] = v;
            }
        const float dd = lam + 0.011f;
        for (int i = 0; i < 6; i++) M[i][i] += dd;
        for (int i = 0; i < 6; i++) gv[i] = sums[21 + i];

        for (int c = 0; c < 6; c++) {
            int piv = c; float mx = fabsf(M[c][c]);
            for (int rr = c + 1; rr < 6; rr++) {
                const float a = fabsf(M[rr][c]);
                if (a > mx) { mx = a; piv = rr; }
            }
            if (piv != c) {
                for (int j = 0; j < 6; j++) {
                    const float tmp = M[c][j]; M[c][j] = M[piv][j]; M[piv][j] = tmp;
                }
                const float tmp = gv[c]; gv[c] = gv[piv]; gv[piv] = tmp;
            }
            float d = M[c][c];
            if (d == 0.f) d = 1e-30f;
            const float invd = 1.0f / d;
            for (int rr = c + 1; rr < 6; rr++) {
                const float f = M[rr][c] * invd;
                for (int j = c; j < 6; j++) M[rr][j] -= f * M[c][j];
                gv[rr] -= f * gv[c];
            }
        }
        for (int i = 5; i >= 0; i--) {
            float s = gv[i];
            for (int j = i + 1; j < 6; j++) s -= M[i][j] * x[j];
            x[i] = s / M[i][i];
        }

#pragma unroll
        for (int i = 0; i < 6; i++) dpsh[i] = x[i];   // unclipped, for depth
        if (slice == 0) {
            for (int i = 0; i < 6; i++)
                out_pose[b * 6 + i] = fminf(fmaxf(x[i], -2.0f), 2.0f);
        }
    }
    __syncthreads();

    float2 dpp[3];
#pragma unroll
    for (int k = 0; k < 3; k++) {
        dpp[k].x = dpsh[2 * k];
        dpp[k].y = dpsh[2 * k + 1];
    }

    // ===================== Phase 3: depth (own batch only) ==================
    for (int i = slice * TPB + threadIdx.x; i < QPB; i += NSLICE * TPB) {
        const size_t p = base + (size_t)i * 4;

        const uint2 fg = *(const uint2*)(g_scrf + p);   // 4x half inv*gd
        const uint4 u0 = *(const uint4*)(g_scrh + 0 * SP + p);
        const uint4 u1 = *(const uint4*)(g_scrh + 1 * SP + p);
        const uint4 u2 = *(const uint4*)(g_scrh + 2 * SP + p);

        const float2 g01 = __half22float2(*(const __half2*)&fg.x);
        const float2 g23 = __half22float2(*(const __half2*)&fg.y);
        float res[4] = {g01.x, g01.y, g23.x, g23.y};

        const uint4 uu[3] = {u0, u1, u2};
#pragma unroll
        for (int k = 0; k < 3; k++) {
            const float2 q0 = __half22float2(*(const __half2*)&uu[k].x);
            const float2 q1 = __half22float2(*(const __half2*)&uu[k].y);
            const float2 q2 = __half22float2(*(const __half2*)&uu[k].z);
            const float2 q3 = __half22float2(*(const __half2*)&uu[k].w);
            res[0] = fmaf(-q0.x, dpp[k].x, fmaf(-q0.y, dpp[k].y, res[0]));
            res[1] = fmaf(-q1.x, dpp[k].x, fmaf(-q1.y, dpp[k].y, res[1]));
            res[2] = fmaf(-q2.x, dpp[k].x, fmaf(-q2.y, dpp[k].y, res[2]));
            res[3] = fmaf(-q3.x, dpp[k].x, fmaf(-q3.y, dpp[k].y, res[3]));
        }

        *(float4*)(out_depth + p) = make_float4(res[0], res[1], res[2], res[3]);
    }
}

// ---------------------------------------------------------------------------
extern "C" void kernel_launch(void* const* d_in, const int* in_sizes, int n_in,
                              void* d_out, int out_size)
{
    const float* r   = (const float*)d_in[0];
    const float* w   = (const float*)d_in[1];
    const float* Jp  = (const float*)d_in[2];
    const float* Jd  = (const float*)d_in[3];
    const float* lam = (const float*)d_in[4];
    float* out = (float*)d_out;

    dba_kernel<<<GRID, TPB>>>(r, w, Jp, Jd, lam, out);
}